// round 12
// baseline (speedup 1.0000x reference)
#include <cuda_runtime.h>
#include <math.h>

// ---------------- problem constants ----------------
#define NVID  4
#define FPV   64
#define TOTF  256
#define NRECS 240
#define TTXT  32
#define EPAD  304      // 300 padded to 304 for float4
#define HIDN  256
#define NCLS  20
#define OCC   32
#define MROWS 7680     // 240*32

typedef unsigned long long u64;

// packed f32x2 helpers (Blackwell sm_103a): bit-exact vs two scalar fmaf
__device__ __forceinline__ u64 pk2(float lo, float hi) {
    u64 r; asm("mov.b64 %0, {%1, %2};" : "=l"(r) : "f"(lo), "f"(hi)); return r;
}
__device__ __forceinline__ void fma2(u64& d, u64 a, u64 b) {
    asm("fma.rn.f32x2 %0, %1, %2, %0;" : "+l"(d) : "l"(a), "l"(b));
}
__device__ __forceinline__ float2 upk2(u64 v) {
    float2 f; asm("mov.b64 {%0, %1}, %2;" : "=f"(f.x), "=f"(f.y) : "l"(v)); return f;
}
__device__ __forceinline__ u64 shift_pair(u64 lo, u64 hi) {
    float2 a = upk2(lo), b = upk2(hi);
    return pk2(a.y, b.x);
}

// ---------------- device-global scratch (allocation-free rule) ----------------
__device__ float g_part[NVID*OCC*FPV*196];   // conv + HW-pool result [v][oc][d][14][14]
__device__ float g_fdot[TOTF*NCLS];          // per-frame pooled-feature . lin_w
__device__ float g_x0[MROWS*EPAD];           // embedded text, K padded
__device__ float g_wpad[2*1024*EPAD];        // Wih_l0 padded 300->304
__device__ float g_pre[2*MROWS*1024];        // input-proj gates per dir
__device__ float g_out0[MROWS*512];          // layer0 output [row][t][512]
__device__ float g_out1[MROWS*512];          // layer1 output
__device__ float g_h[2][2][NRECS*HIDN];      // [parity][dir][row*256+j]
__device__ float g_avg[NRECS*512];
__device__ unsigned g_sync[2][15];           // lstm cross-CTA barrier counters

// ================= Conv3D + HW max-pool (fused) =================
// grid (14 ph, 32 dpair, z = v*4 + half*2 + ocb), 448 threads, 2 CTAs/SM.
// Thread: dloc(2) x pwl(7) x ocg(4) x hh(8); acc = 4 oc x 8 ow (32 regs).
// smem: even/odd parity patch (stride 62) + (w,w)-duplicated u64 weights [q=441][16].
#define PHALF (84*62)                          // 5208 floats per parity plane
#define WQ 441
#define CONV_SMEM (2*PHALF*4 + WQ*16*8)        // 41664 + 56448 = 98112 B

__device__ __forceinline__ void load_patch(
    float* stage, int ci, const float* __restrict__ img,
    int v, int d0, int ph, int half, int tid)
{
    const int NL = 4*21*117;
    for (int i = tid; i < NL; i += 448) {
        int c  = i % 117; int rr = i / 117;
        int r  = rr % 21; int dds = rr / 21;
        int iw = 112*half - 3 + c;
        int ih = 16*ph    - 3 + r;
        int dd = d0 - 1 + dds;
        float val = 0.f;
        if ((unsigned)dd < 64u && (unsigned)ih < 224u && (unsigned)iw < 224u)
            val = img[(((v*64 + dd)*3 + ci)*224 + ih)*224 + iw];
        stage[(c & 1)*PHALF + (dds*21 + r)*62 + (c >> 1)] = val;
    }
}

__global__ __launch_bounds__(448,2) void conv_pool_kernel(
    const float* __restrict__ img, const float* __restrict__ cw)
{
    extern __shared__ float sh[];
    u64* wd = (u64*)(sh + 2*PHALF);            // [q][16] (w,w) pairs
    const int ph = blockIdx.x;
    const int d0 = blockIdx.y * 2;
    const int z  = blockIdx.z;
    const int v = z >> 2, half = (z >> 1) & 1, ocb = z & 1;
    const int tid = threadIdx.x;

    for (int i = tid; i < WQ*16; i += 448) {
        int q = i >> 4, l = i & 15;
        float w = cw[(ocb*16 + l)*WQ + q];
        wd[i] = pk2(w, w);
    }

    const int dloc = tid / 224; const int rem = tid % 224;
    const int pwl  = rem >> 5;  const int lane = rem & 31;
    const int ocg  = lane >> 3; const int hh  = lane & 7;

    u64 acc[4][4];
    #pragma unroll
    for (int r = 0; r < 4; r++)
        #pragma unroll
        for (int p = 0; p < 4; p++) acc[r][p] = 0ull;

    for (int ci = 0; ci < 3; ci++) {
        __syncthreads();
        load_patch(sh, ci, img, v, d0, ph, half, tid);
        __syncthreads();
        const float* pe = sh;
        const float* po = sh + PHALF;

        for (int kd = 0; kd < 3; kd++)
        #pragma unroll 1
        for (int kh = 0; kh < 7; kh++) {
            const int rowi = ((dloc + kd)*21 + 2*hh + kh)*62 + 8*pwl;
            const u64* peu = (const u64*)(pe + rowi);
            const u64* pou = (const u64*)(po + rowi);
            u64 ev[6], od[6];
            #pragma unroll
            for (int q = 0; q < 6; q++) { ev[q] = peu[q]; od[q] = pou[q]; }
            const u64* wq = wd + (ci*147 + kd*49 + kh*7)*16 + ocg*4;
            #pragma unroll
            for (int kw = 0; kw < 7; kw++) {
                const int s  = kw >> 1;
                const int i0 = s >> 1;
                u64 xp2[4];
                #pragma unroll
                for (int t2 = 0; t2 < 4; t2++) {
                    if (kw & 1)
                        xp2[t2] = (s & 1) ? shift_pair(od[i0 + t2], od[i0 + t2 + 1])
                                          : od[i0 + t2];
                    else
                        xp2[t2] = (s & 1) ? shift_pair(ev[i0 + t2], ev[i0 + t2 + 1])
                                          : ev[i0 + t2];
                }
                const u64* wrow = wq + kw*16;
                ulonglong2 w01 = *(const ulonglong2*)(wrow);
                ulonglong2 w23 = *(const ulonglong2*)(wrow + 2);
                #pragma unroll
                for (int j = 0; j < 4; j++) fma2(acc[0][j], w01.x, xp2[j]);
                #pragma unroll
                for (int j = 0; j < 4; j++) fma2(acc[1][j], w01.y, xp2[j]);
                #pragma unroll
                for (int j = 0; j < 4; j++) fma2(acc[2][j], w23.x, xp2[j]);
                #pragma unroll
                for (int j = 0; j < 4; j++) fma2(acc[3][j], w23.y, xp2[j]);
            }
        }
    }

    const int d  = d0 + dloc;
    const int pw = half*7 + pwl;
    #pragma unroll
    for (int r = 0; r < 4; r++) {
        float2 f0 = upk2(acc[r][0]);
        float mx = fmaxf(f0.x, f0.y);
        #pragma unroll
        for (int p = 1; p < 4; p++) {
            float2 fp = upk2(acc[r][p]);
            mx = fmaxf(mx, fmaxf(fp.x, fp.y));
        }
        mx = fmaxf(mx, __shfl_xor_sync(0xffffffffu, mx, 4));
        mx = fmaxf(mx, __shfl_xor_sync(0xffffffffu, mx, 2));
        mx = fmaxf(mx, __shfl_xor_sync(0xffffffffu, mx, 1));
        if (hh == 0) {
            int oc = ocb*16 + ocg*4 + r;
            g_part[(((v*OCC + oc)*FPV + d)*14 + ph)*14 + pw] = mx;
        }
    }
}

// ================= D-pool + (pooled features) . lin_w -> g_fdot =================
__global__ void fdot_kernel(const float* __restrict__ cb, const float* __restrict__ lw)
{
    const int f = blockIdx.x;            // 256
    const int v = f >> 6, d = f & 63;
    const int tid = threadIdx.x;         // 256
    float acc[NCLS];
    #pragma unroll
    for (int c = 0; c < NCLS; c++) acc[c] = 0.f;

    for (int k = tid; k < 6272; k += 256) {
        int oc = k / 196; int rem2 = k % 196;
        const float* base = g_part + (v*OCC + oc)*FPV*196 + rem2;
        float val = base[d*196];
        if (d > 0)  val = fmaxf(val, base[(d-1)*196]);
        if (d < 63) val = fmaxf(val, base[(d+1)*196]);
        val += cb[oc];
        #pragma unroll
        for (int c = 0; c < NCLS; c++) acc[c] = fmaf(val, lw[c*6784 + k], acc[c]);
    }
    #pragma unroll
    for (int c = 0; c < NCLS; c++)
        for (int off = 16; off; off >>= 1)
            acc[c] += __shfl_xor_sync(0xffffffffu, acc[c], off);

    __shared__ float red[8][NCLS];
    const int wid = tid >> 5, lane = tid & 31;
    if (lane == 0)
        #pragma unroll
        for (int c = 0; c < NCLS; c++) red[wid][c] = acc[c];
    __syncthreads();
    if (tid < NCLS) {
        float s = 0.f;
        #pragma unroll
        for (int w = 0; w < 8; w++) s += red[w][tid];
        g_fdot[f*NCLS + tid] = s;
    }
}

// ================= Embedding gather (pad K to 304) =================
__global__ void embed_kernel(const int* __restrict__ txt, const float* __restrict__ emb)
{
    const int m = blockIdx.x;            // 7680 = row*32 + t
    const int tok = txt[m];
    const float* e = emb + (long long)tok * 300;
    for (int k = threadIdx.x; k < EPAD; k += 128)
        g_x0[m*EPAD + k] = (k < 300) ? e[k] : 0.f;
}

__global__ void pad_wih_kernel(const float* __restrict__ Wih0)
{
    const int row = blockIdx.x;          // 2048 = dir*1024 + gate
    const float* src = Wih0 + row * 300;
    for (int k = threadIdx.x; k < EPAD; k += 128)
        g_wpad[row*EPAD + k] = (k < 300) ? src[k] : 0.f;
}

// ================= SGEMM: pre = X @ Wih^T + bih + bhh =================
__global__ __launch_bounds__(256,2) void gemm_kernel(
    int layer, const float* __restrict__ Bext,
    const float* __restrict__ bih, const float* __restrict__ bhh)
{
    const int K = layer ? 512 : EPAD;
    const float* A = layer ? g_out0 : g_x0;
    const float* B = (layer ? Bext : (const float*)g_wpad) + blockIdx.z * 1024 * K;
    float* C = g_pre + blockIdx.z * (MROWS * 1024);
    const int m0 = blockIdx.x * 128, n0 = blockIdx.y * 128;

    __shared__ float As[8*132];
    __shared__ float Bs[8*132];
    const int tid = threadIdx.x;
    const int lr = tid >> 1;
    const int lk = (tid & 1) * 4;
    const int ty = tid >> 4, tx = tid & 15;
    const float* Arow = A + (m0 + lr)*K + lk;
    const float* Brow = B + (n0 + lr)*K + lk;

    u64 accp[8][4];
    #pragma unroll
    for (int i = 0; i < 8; i++)
        #pragma unroll
        for (int p = 0; p < 4; p++) accp[i][p] = 0ull;

    for (int k0 = 0; k0 < K; k0 += 8) {
        float4 va = *(const float4*)(Arow + k0);
        float4 vb = *(const float4*)(Brow + k0);
        __syncthreads();
        As[(lk+0)*132 + lr] = va.x; As[(lk+1)*132 + lr] = va.y;
        As[(lk+2)*132 + lr] = va.z; As[(lk+3)*132 + lr] = va.w;
        Bs[(lk+0)*132 + lr] = vb.x; Bs[(lk+1)*132 + lr] = vb.y;
        Bs[(lk+2)*132 + lr] = vb.z; Bs[(lk+3)*132 + lr] = vb.w;
        __syncthreads();
        #pragma unroll
        for (int kk = 0; kk < 8; kk++) {
            float a[8];
            float4 t0 = *(const float4*)&As[kk*132 + ty*8];
            float4 t1 = *(const float4*)&As[kk*132 + ty*8 + 4];
            float4 t2 = *(const float4*)&Bs[kk*132 + tx*8];
            float4 t3 = *(const float4*)&Bs[kk*132 + tx*8 + 4];
            a[0]=t0.x;a[1]=t0.y;a[2]=t0.z;a[3]=t0.w;a[4]=t1.x;a[5]=t1.y;a[6]=t1.z;a[7]=t1.w;
            u64 bp[4];
            bp[0] = pk2(t2.x, t2.y); bp[1] = pk2(t2.z, t2.w);
            bp[2] = pk2(t3.x, t3.y); bp[3] = pk2(t3.z, t3.w);
            #pragma unroll
            for (int i = 0; i < 8; i++) {
                u64 a2 = pk2(a[i], a[i]);
                #pragma unroll
                for (int p = 0; p < 4; p++) fma2(accp[i][p], a2, bp[p]);
            }
        }
    }
    float bb[8];
    #pragma unroll
    for (int j = 0; j < 8; j++) {
        int n = n0 + tx*8 + j;
        bb[j] = bih[blockIdx.z*1024 + n] + bhh[blockIdx.z*1024 + n];
    }
    #pragma unroll
    for (int i = 0; i < 8; i++) {
        float* crow = C + (m0 + ty*8 + i)*1024 + n0 + tx*8;
        #pragma unroll
        for (int p = 0; p < 4; p++) {
            float2 f = upk2(accp[i][p]);
            crow[2*p]   = f.x + bb[2*p];
            crow[2*p+1] = f.y + bb[2*p+1];
        }
    }
}

// ================= LSTM: persistent 32-step kernel =================
__global__ void zero_sync_kernel()
{
    int i = threadIdx.x;
    if (i < 30) ((unsigned*)g_sync)[i] = 0u;
}

__global__ __launch_bounds__(256,1) void lstm_seq(
    int layer, const float* __restrict__ Whh, const int* __restrict__ lens)
{
    const int r0  = blockIdx.x * 16;
    const int j0  = blockIdx.y * 64;
    const int dir = blockIdx.z;
    const float* pre = g_pre + dir * (MROWS * 1024);
    float* outb = layer ? g_out1 : g_out0;

    __shared__ float hs2[256][18];   // [k][row-local], 8B-aligned row pairs
    __shared__ float zs[4][64][17];  // [gate][jl][row-local]
    __shared__ float cs[16][64];     // cell state, lives here all 32 steps
    const int tid = threadIdx.x;
    const int jl = tid & 63, gt = tid >> 6;
    const int gidx = gt*256 + j0 + jl;
    const float* wrow = Whh + dir*1024*256 + gidx*256;
    volatile unsigned* ctr = &g_sync[dir][blockIdx.x];

    for (int i = tid; i < 4096; i += 256) hs2[i & 255][i >> 8] = 0.f;
    for (int i = tid; i < 1024; i += 256) cs[i >> 6][i & 63] = 0.f;
    __syncthreads();

    for (int s = 0; s < 32; s++) {
        const int t = dir ? (31 - s) : s;

        u64 accp[8];
        #pragma unroll
        for (int q = 0; q < 8; q++)
            accp[q] = pk2(pre[((r0 + 2*q)*32 + t)*1024 + gidx],
                          pre[((r0 + 2*q + 1)*32 + t)*1024 + gidx]);

        #pragma unroll 2
        for (int k0 = 0; k0 < 256; k0 += 4) {
            float4 w = *(const float4*)(wrow + k0);
            float wk[4] = {w.x, w.y, w.z, w.w};
            #pragma unroll
            for (int kk = 0; kk < 4; kk++) {
                u64 w2 = pk2(wk[kk], wk[kk]);
                const u64* hrow = (const u64*)&hs2[k0 + kk][0];
                #pragma unroll
                for (int q = 0; q < 8; q++) fma2(accp[q], w2, hrow[q]);
            }
        }
        #pragma unroll
        for (int q = 0; q < 8; q++) {
            float2 f = upk2(accp[q]);
            zs[gt][jl][2*q]   = f.x;
            zs[gt][jl][2*q+1] = f.y;
        }
        __syncthreads();

        float* hn = g_h[(s + 1) & 1][dir];
        #pragma unroll
        for (int q = 0; q < 4; q++) {
            int cell = tid + 256*q;
            int jl2 = cell & 63, rr = cell >> 6;
            int row = r0 + rr, j = j0 + jl2;
            float zi = zs[0][jl2][rr], zf = zs[1][jl2][rr];
            float zg = zs[2][jl2][rr], zo = zs[3][jl2][rr];
            float c_old = cs[rr][jl2];
            float h_old = hs2[j][rr];
            bool m = t < lens[row];
            float si = 1.f / (1.f + expf(-zi));
            float sf = 1.f / (1.f + expf(-zf));
            float so = 1.f / (1.f + expf(-zo));
            float cn = sf*c_old + si*tanhf(zg);
            float hv = so*tanhf(cn);
            cs[rr][jl2] = m ? cn : c_old;
            hn[row*256 + j] = m ? hv : h_old;
            outb[(row*32 + t)*512 + dir*256 + j] = m ? hv : 0.f;
        }

        if (s < 31) {
            __threadfence();
            __syncthreads();
            if (tid == 0) {
                atomicAdd((unsigned*)ctr, 1u);
                while (*ctr < 4u*(s + 1)) { }
            }
            __syncthreads();
            const float* hp = g_h[(s + 1) & 1][dir];
            for (int i = tid; i < 4096; i += 256) {
                int r = i >> 8, k = i & 255;
                hs2[k][r] = __ldcg(&hp[(r0 + r)*256 + k]);
            }
            __syncthreads();
        }
    }
}

// ================= masked mean over time =================
__global__ void avg_kernel(const int* __restrict__ lens)
{
    const int row = blockIdx.x;   // 240
    const int k = threadIdx.x;    // 512
    float s = 0.f;
    for (int t = 0; t < 32; t++) s += g_out1[(row*32 + t)*512 + k];
    g_avg[row*512 + k] = s / (float)lens[row];
}

// ================= logits + per-video max + sigmoid =================
__global__ void final_kernel(const float* __restrict__ lw, const float* __restrict__ lb,
                             float* __restrict__ out)
{
    const int v = blockIdx.x / NCLS, c = blockIdx.x % NCLS;
    const int tid = threadIdx.x;  // 64
    float lg = -1e30f;
    if (tid < 60) {
        int rec = v*60 + tid;
        int sg = tid / 15, pp = tid % 15;
        int f = v*64 + sg*16 + pp;
        const float* av = g_avg + rec*512;
        const float* w  = lw + c*6784 + 6272;
        float dot = 0.f;
        #pragma unroll 4
        for (int k = 0; k < 512; k++) dot += av[k]*w[k];
        lg = 0.5f*(g_fdot[f*NCLS + c] + g_fdot[(f+1)*NCLS + c]) + dot + lb[c];
    }
    for (int off = 16; off; off >>= 1)
        lg = fmaxf(lg, __shfl_xor_sync(0xffffffffu, lg, off));
    __shared__ float red[2];
    if ((tid & 31) == 0) red[tid >> 5] = lg;
    __syncthreads();
    if (tid == 0) {
        float m = fmaxf(red[0], red[1]);
        out[v*NCLS + c] = 1.f / (1.f + expf(-m));
    }
}

// ================= launch =================
// Fork-join: conv+fdot on side stream s1. conv is my kernel #4 (overall #6 for ncu).
extern "C" void kernel_launch(void* const* d_in, const int* in_sizes, int n_in,
                              void* d_out, int out_size)
{
    const float* img  = (const float*)d_in[0];
    const int*   txt  = (const int*)d_in[1];
    const int*   lens = (const int*)d_in[2];
    const float* emb  = (const float*)d_in[7];
    const float* Wih0 = (const float*)d_in[8];
    const float* Whh0 = (const float*)d_in[9];
    const float* bih0 = (const float*)d_in[10];
    const float* bhh0 = (const float*)d_in[11];
    const float* Wih1 = (const float*)d_in[12];
    const float* Whh1 = (const float*)d_in[13];
    const float* bih1 = (const float*)d_in[14];
    const float* bhh1 = (const float*)d_in[15];
    const float* cw   = (const float*)d_in[16];
    const float* cb   = (const float*)d_in[17];
    const float* lw   = (const float*)d_in[18];
    const float* lb   = (const float*)d_in[19];
    float* out = (float*)d_out;

    static cudaStream_t s1 = nullptr;
    static cudaEvent_t evF = nullptr, evJ = nullptr;
    if (s1 == nullptr) {
        cudaStreamCreateWithFlags(&s1, cudaStreamNonBlocking);
        cudaEventCreateWithFlags(&evF, cudaEventDisableTiming);
        cudaEventCreateWithFlags(&evJ, cudaEventDisableTiming);
        cudaFuncSetAttribute(conv_pool_kernel,
                             cudaFuncAttributeMaxDynamicSharedMemorySize, CONV_SMEM);
    }

    pad_wih_kernel<<<2048, 128>>>(Wih0);                          // my #1 (stream 0)
    embed_kernel<<<7680, 128>>>(txt, emb);                        // my #2 (stream 0)
    gemm_kernel<<<dim3(60,8,2), 256>>>(0, (const float*)nullptr, bih0, bhh0); // my #3

    cudaEventRecord(evF, 0);
    cudaStreamWaitEvent(s1, evF, 0);
    conv_pool_kernel<<<dim3(14,32,16), 448, CONV_SMEM, s1>>>(img, cw); // my #4 <- profiled
    fdot_kernel<<<256, 256, 0, s1>>>(cb, lw);                     // my #5 (s1)

    zero_sync_kernel<<<1, 32>>>();
    lstm_seq<<<dim3(15,4,2), 256>>>(0, Whh0, lens);
    gemm_kernel<<<dim3(60,8,2), 256>>>(1, Wih1, bih1, bhh1);
    zero_sync_kernel<<<1, 32>>>();
    lstm_seq<<<dim3(15,4,2), 256>>>(1, Whh1, lens);
    avg_kernel<<<240, 512>>>(lens);

    cudaEventRecord(evJ, s1);
    cudaStreamWaitEvent(0, evJ, 0);
    final_kernel<<<80, 64>>>(lw, lb, out);
}

// round 14
// speedup vs baseline: 1.0653x; 1.0653x over previous
#include <cuda_runtime.h>
#include <math.h>

// ---------------- problem constants ----------------
#define NVID  4
#define FPV   64
#define TOTF  256
#define NRECS 240
#define TTXT  32
#define EPAD  304
#define HIDN  256
#define NCLS  20
#define OCC   32
#define MROWS 7680

typedef unsigned long long u64;

__device__ __forceinline__ u64 pk2(float lo, float hi) {
    u64 r; asm("mov.b64 %0, {%1, %2};" : "=l"(r) : "f"(lo), "f"(hi)); return r;
}
__device__ __forceinline__ void fma2(u64& d, u64 a, u64 b) {
    asm("fma.rn.f32x2 %0, %1, %2, %0;" : "+l"(d) : "l"(a), "l"(b));
}
__device__ __forceinline__ float2 upk2(u64 v) {
    float2 f; asm("mov.b64 {%0, %1}, %2;" : "=f"(f.x), "=f"(f.y) : "l"(v)); return f;
}

// ---------------- device-global scratch ----------------
__device__ float g_part[NVID*OCC*FPV*196];
__device__ float g_fdot[TOTF*NCLS];
__device__ float g_x0[MROWS*EPAD];
__device__ float g_wpad[2*1024*EPAD];
__device__ float g_pre[2*MROWS*1024];
__device__ float g_out0[MROWS*512];
__device__ float g_out1[MROWS*512];
__device__ float g_h[2][2][NRECS*HIDN];
__device__ float g_avg[NRECS*512];
__device__ unsigned g_sync[2][15];

// ================= Conv3D + HW max-pool via tf32 mma.sync =================
// grid (14 ph, 64 d, v*2+half), 224 threads = 7 warps (one per 8-wide pool col).
// CTA computes conv outputs h = 8ph..8ph+7, w = 56*half..+55, all 32 oc, one d.
// S: input slab [h'21][ci4][w'128] (tf32 bits, w' xor-swizzled by ci<<3), per-kd refill.
// W: weights [(kd*7+kh)*4+p][k8][40] tf32 (k = kwo*4+ci, kw = 2p+kwo; pads zeroed).
#define S_WORDS (21*4*128)          // 10752
#define W_WORDS (21*4*8*40)         // 26880
#define CONV_SMEM ((S_WORDS + W_WORDS)*4)   // 150528 B

__global__ __launch_bounds__(224,1) void conv_mma_kernel(
    const float* __restrict__ img, const float* __restrict__ cw)
{
    extern __shared__ float sh[];
    float* S = sh;
    float* W = sh + S_WORDS;
    const int ph = blockIdx.x;
    const int d  = blockIdx.y;
    const int v  = blockIdx.z >> 1, half = blockIdx.z & 1;
    const int tid = threadIdx.x;
    const int lane = tid & 31, wp = tid >> 5;
    const int wm = lane >> 2, qi = lane & 3;

    // ---- weight fill (tf32 bits) ----
    for (int i = tid; i < 21*4*8*32; i += 224) {
        int oc = i & 31; int rr = i >> 5;
        int k = rr & 7;  rr >>= 3;
        int p = rr & 3;  int kdkh = rr >> 2;
        int kd = kdkh / 7, kh = kdkh % 7;
        int kw = 2*p + (k >> 2), ci = k & 3;
        float val = 0.f;
        if (kw < 7 && ci < 3)
            val = cw[(((oc*3 + ci)*3 + kd)*7 + kh)*7 + kw];
        unsigned uv; asm("cvt.rna.tf32.f32 %0, %1;" : "=r"(uv) : "f"(val));
        W[((kdkh*4 + p)*8 + k)*40 + oc] = __uint_as_float(uv);
    }

    float c[4][4][4];
    #pragma unroll
    for (int mt = 0; mt < 4; mt++)
        #pragma unroll
        for (int nt = 0; nt < 4; nt++)
            #pragma unroll
            for (int r = 0; r < 4; r++) c[mt][nt][r] = 0.f;

    const int wbase = 2*(wp*8 + wm);
    const int sw = qi << 3;

    for (int kd = 0; kd < 3; kd++) {
        __syncthreads();
        int d_in = d + kd - 1;
        for (int i = tid; i < 21*4*118; i += 224) {
            int w = i % 118; int rr = i / 118;
            int ci = rr & 3; int hp = rr >> 2;
            float val = 0.f;
            if (ci < 3 && (unsigned)d_in < 64u) {
                int h_in = 16*ph - 3 + hp;
                int w_in = 112*half - 3 + w;
                if ((unsigned)h_in < 224u && (unsigned)w_in < 224u)
                    val = img[(((v*64 + d_in)*3 + ci)*224 + h_in)*224 + w_in];
            }
            unsigned uv; asm("cvt.rna.tf32.f32 %0, %1;" : "=r"(uv) : "f"(val));
            S[(hp*4 + ci)*128 + (w ^ (ci << 3))] = __uint_as_float(uv);
        }
        __syncthreads();

        for (int kh = 0; kh < 7; kh++) {
            // B fragments for all 4 kw-pairs x 4 oc-tiles
            unsigned b[4][4][2];
            const float* Wb = W + (kd*7 + kh)*4*8*40;
            #pragma unroll
            for (int p = 0; p < 4; p++)
                #pragma unroll
                for (int nt = 0; nt < 4; nt++) {
                    b[p][nt][0] = __float_as_uint(Wb[(p*8 + qi)*40 + nt*8 + wm]);
                    b[p][nt][1] = __float_as_uint(Wb[(p*8 + qi + 4)*40 + nt*8 + wm]);
                }
            #pragma unroll
            for (int mt = 0; mt < 4; mt++) {
                const float* A0 = S + ((4*mt + kh)*4 + qi)*128;
                const float* A1 = A0 + 2*4*128;
                float2 p0[4], p1[4];
                #pragma unroll
                for (int j = 0; j < 4; j++) {
                    p0[j] = *(const float2*)&A0[(wbase + 2*j) ^ sw];
                    p1[j] = *(const float2*)&A1[(wbase + 2*j) ^ sw];
                }
                #pragma unroll
                for (int p = 0; p < 4; p++) {
                    unsigned ra0 = __float_as_uint(p0[p].x);
                    unsigned ra2 = __float_as_uint(p0[p].y);
                    unsigned ra1 = __float_as_uint(p1[p].x);
                    unsigned ra3 = __float_as_uint(p1[p].y);
                    #pragma unroll
                    for (int nt = 0; nt < 4; nt++)
                        asm volatile(
                          "mma.sync.aligned.m16n8k8.row.col.f32.tf32.tf32.f32 "
                          "{%0,%1,%2,%3},{%4,%5,%6,%7},{%8,%9},{%0,%1,%2,%3};"
                          : "+f"(c[mt][nt][0]), "+f"(c[mt][nt][1]),
                            "+f"(c[mt][nt][2]), "+f"(c[mt][nt][3])
                          : "r"(ra0), "r"(ra1), "r"(ra2), "r"(ra3),
                            "r"(b[p][nt][0]), "r"(b[p][nt][1]));
                }
            }
        }
    }

    // ---- HW max-pool epilogue ----
    const int pw = half*7 + wp;
    #pragma unroll
    for (int nt = 0; nt < 4; nt++) {
        float m0 = -1e30f, m1 = -1e30f;
        #pragma unroll
        for (int mt = 0; mt < 4; mt++) {
            m0 = fmaxf(m0, fmaxf(c[mt][nt][0], c[mt][nt][2]));
            m1 = fmaxf(m1, fmaxf(c[mt][nt][1], c[mt][nt][3]));
        }
        #pragma unroll
        for (int off = 16; off >= 4; off >>= 1) {
            m0 = fmaxf(m0, __shfl_xor_sync(0xffffffffu, m0, off));
            m1 = fmaxf(m1, __shfl_xor_sync(0xffffffffu, m1, off));
        }
        if (wm == 0) {
            int oc = nt*8 + qi*2;
            int base = ((v*OCC + oc)*FPV + d)*196 + ph*14 + pw;
            g_part[base] = m0;
            g_part[base + FPV*196] = m1;   // oc+1
        }
    }
}

// ================= D-pool + (pooled features) . lin_w -> g_fdot =================
__global__ void fdot_kernel(const float* __restrict__ cb, const float* __restrict__ lw)
{
    const int f = blockIdx.x;
    const int v = f >> 6, d = f & 63;
    const int tid = threadIdx.x;
    float acc[NCLS];
    #pragma unroll
    for (int c = 0; c < NCLS; c++) acc[c] = 0.f;

    for (int k = tid; k < 6272; k += 256) {
        int oc = k / 196; int rem2 = k % 196;
        const float* base = g_part + (v*OCC + oc)*FPV*196 + rem2;
        float val = base[d*196];
        if (d > 0)  val = fmaxf(val, base[(d-1)*196]);
        if (d < 63) val = fmaxf(val, base[(d+1)*196]);
        val += cb[oc];
        #pragma unroll
        for (int c = 0; c < NCLS; c++) acc[c] = fmaf(val, lw[c*6784 + k], acc[c]);
    }
    #pragma unroll
    for (int c = 0; c < NCLS; c++)
        for (int off = 16; off; off >>= 1)
            acc[c] += __shfl_xor_sync(0xffffffffu, acc[c], off);

    __shared__ float red[8][NCLS];
    const int wid = tid >> 5, lane = tid & 31;
    if (lane == 0)
        #pragma unroll
        for (int c = 0; c < NCLS; c++) red[wid][c] = acc[c];
    __syncthreads();
    if (tid < NCLS) {
        float s = 0.f;
        #pragma unroll
        for (int w = 0; w < 8; w++) s += red[w][tid];
        g_fdot[f*NCLS + tid] = s;
    }
}

// ================= Embedding gather =================
__global__ void embed_kernel(const int* __restrict__ txt, const float* __restrict__ emb)
{
    const int m = blockIdx.x;
    const int tok = txt[m];
    const float* e = emb + (long long)tok * 300;
    for (int k = threadIdx.x; k < EPAD; k += 128)
        g_x0[m*EPAD + k] = (k < 300) ? e[k] : 0.f;
}

__global__ void pad_wih_kernel(const float* __restrict__ Wih0)
{
    const int row = blockIdx.x;
    const float* src = Wih0 + row * 300;
    for (int k = threadIdx.x; k < EPAD; k += 128)
        g_wpad[row*EPAD + k] = (k < 300) ? src[k] : 0.f;
}

// ================= SGEMM: pre = X @ Wih^T + bih + bhh =================
__global__ __launch_bounds__(256,2) void gemm_kernel(
    int layer, const float* __restrict__ Bext,
    const float* __restrict__ bih, const float* __restrict__ bhh)
{
    const int K = layer ? 512 : EPAD;
    const float* A = layer ? g_out0 : g_x0;
    const float* B = (layer ? Bext : (const float*)g_wpad) + blockIdx.z * 1024 * K;
    float* C = g_pre + blockIdx.z * (MROWS * 1024);
    const int m0 = blockIdx.x * 128, n0 = blockIdx.y * 128;

    __shared__ float As[8*132];
    __shared__ float Bs[8*132];
    const int tid = threadIdx.x;
    const int lr = tid >> 1;
    const int lk = (tid & 1) * 4;
    const int ty = tid >> 4, tx = tid & 15;
    const float* Arow = A + (m0 + lr)*K + lk;
    const float* Brow = B + (n0 + lr)*K + lk;

    u64 accp[8][4];
    #pragma unroll
    for (int i = 0; i < 8; i++)
        #pragma unroll
        for (int p = 0; p < 4; p++) accp[i][p] = 0ull;

    for (int k0 = 0; k0 < K; k0 += 8) {
        float4 va = *(const float4*)(Arow + k0);
        float4 vb = *(const float4*)(Brow + k0);
        __syncthreads();
        As[(lk+0)*132 + lr] = va.x; As[(lk+1)*132 + lr] = va.y;
        As[(lk+2)*132 + lr] = va.z; As[(lk+3)*132 + lr] = va.w;
        Bs[(lk+0)*132 + lr] = vb.x; Bs[(lk+1)*132 + lr] = vb.y;
        Bs[(lk+2)*132 + lr] = vb.z; Bs[(lk+3)*132 + lr] = vb.w;
        __syncthreads();
        #pragma unroll
        for (int kk = 0; kk < 8; kk++) {
            float a[8];
            float4 t0 = *(const float4*)&As[kk*132 + ty*8];
            float4 t1 = *(const float4*)&As[kk*132 + ty*8 + 4];
            float4 t2 = *(const float4*)&Bs[kk*132 + tx*8];
            float4 t3 = *(const float4*)&Bs[kk*132 + tx*8 + 4];
            a[0]=t0.x;a[1]=t0.y;a[2]=t0.z;a[3]=t0.w;a[4]=t1.x;a[5]=t1.y;a[6]=t1.z;a[7]=t1.w;
            u64 bp[4];
            bp[0] = pk2(t2.x, t2.y); bp[1] = pk2(t2.z, t2.w);
            bp[2] = pk2(t3.x, t3.y); bp[3] = pk2(t3.z, t3.w);
            #pragma unroll
            for (int i = 0; i < 8; i++) {
                u64 a2 = pk2(a[i], a[i]);
                #pragma unroll
                for (int p = 0; p < 4; p++) fma2(accp[i][p], a2, bp[p]);
            }
        }
    }
    float bb[8];
    #pragma unroll
    for (int j = 0; j < 8; j++) {
        int n = n0 + tx*8 + j;
        bb[j] = bih[blockIdx.z*1024 + n] + bhh[blockIdx.z*1024 + n];
    }
    #pragma unroll
    for (int i = 0; i < 8; i++) {
        float* crow = C + (m0 + ty*8 + i)*1024 + n0 + tx*8;
        #pragma unroll
        for (int p = 0; p < 4; p++) {
            float2 f = upk2(accp[i][p]);
            crow[2*p]   = f.x + bb[2*p];
            crow[2*p+1] = f.y + bb[2*p+1];
        }
    }
}

// ================= LSTM: persistent 32-step kernel =================
__global__ void zero_sync_kernel()
{
    int i = threadIdx.x;
    if (i < 30) ((unsigned*)g_sync)[i] = 0u;
}

__global__ __launch_bounds__(256,1) void lstm_seq(
    int layer, const float* __restrict__ Whh, const int* __restrict__ lens)
{
    const int r0  = blockIdx.x * 16;
    const int j0  = blockIdx.y * 64;
    const int dir = blockIdx.z;
    const float* pre = g_pre + dir * (MROWS * 1024);
    float* outb = layer ? g_out1 : g_out0;

    __shared__ float hs2[256][18];
    __shared__ float zs[4][64][17];
    __shared__ float cs[16][64];
    const int tid = threadIdx.x;
    const int jl = tid & 63, gt = tid >> 6;
    const int gidx = gt*256 + j0 + jl;
    const float* wrow = Whh + dir*1024*256 + gidx*256;
    volatile unsigned* ctr = &g_sync[dir][blockIdx.x];

    for (int i = tid; i < 4096; i += 256) hs2[i & 255][i >> 8] = 0.f;
    for (int i = tid; i < 1024; i += 256) cs[i >> 6][i & 63] = 0.f;
    __syncthreads();

    for (int s = 0; s < 32; s++) {
        const int t = dir ? (31 - s) : s;

        u64 accp[8];
        #pragma unroll
        for (int q = 0; q < 8; q++)
            accp[q] = pk2(pre[((r0 + 2*q)*32 + t)*1024 + gidx],
                          pre[((r0 + 2*q + 1)*32 + t)*1024 + gidx]);

        #pragma unroll 2
        for (int k0 = 0; k0 < 256; k0 += 4) {
            float4 w = *(const float4*)(wrow + k0);
            float wk[4] = {w.x, w.y, w.z, w.w};
            #pragma unroll
            for (int kk = 0; kk < 4; kk++) {
                u64 w2 = pk2(wk[kk], wk[kk]);
                const u64* hrow = (const u64*)&hs2[k0 + kk][0];
                #pragma unroll
                for (int q = 0; q < 8; q++) fma2(accp[q], w2, hrow[q]);
            }
        }
        #pragma unroll
        for (int q = 0; q < 8; q++) {
            float2 f = upk2(accp[q]);
            zs[gt][jl][2*q]   = f.x;
            zs[gt][jl][2*q+1] = f.y;
        }
        __syncthreads();

        float* hn = g_h[(s + 1) & 1][dir];
        #pragma unroll
        for (int q = 0; q < 4; q++) {
            int cell = tid + 256*q;
            int jl2 = cell & 63, rr = cell >> 6;
            int row = r0 + rr, j = j0 + jl2;
            float zi = zs[0][jl2][rr], zf = zs[1][jl2][rr];
            float zg = zs[2][jl2][rr], zo = zs[3][jl2][rr];
            float c_old = cs[rr][jl2];
            float h_old = hs2[j][rr];
            bool m = t < lens[row];
            float si = 1.f / (1.f + expf(-zi));
            float sf = 1.f / (1.f + expf(-zf));
            float so = 1.f / (1.f + expf(-zo));
            float cn = sf*c_old + si*tanhf(zg);
            float hv = so*tanhf(cn);
            cs[rr][jl2] = m ? cn : c_old;
            hn[row*256 + j] = m ? hv : h_old;
            outb[(row*32 + t)*512 + dir*256 + j] = m ? hv : 0.f;
        }

        if (s < 31) {
            __threadfence();
            __syncthreads();
            if (tid == 0) {
                atomicAdd((unsigned*)ctr, 1u);
                while (*ctr < 4u*(s + 1)) { }
            }
            __syncthreads();
            const float* hp = g_h[(s + 1) & 1][dir];
            for (int i = tid; i < 4096; i += 256) {
                int r = i >> 8, k = i & 255;
                hs2[k][r] = __ldcg(&hp[(r0 + r)*256 + k]);
            }
            __syncthreads();
        }
    }
}

// ================= masked mean over time =================
__global__ void avg_kernel(const int* __restrict__ lens)
{
    const int row = blockIdx.x;
    const int k = threadIdx.x;
    float s = 0.f;
    for (int t = 0; t < 32; t++) s += g_out1[(row*32 + t)*512 + k];
    g_avg[row*512 + k] = s / (float)lens[row];
}

// ================= logits + per-video max + sigmoid =================
__global__ void final_kernel(const float* __restrict__ lw, const float* __restrict__ lb,
                             float* __restrict__ out)
{
    const int v = blockIdx.x / NCLS, c = blockIdx.x % NCLS;
    const int tid = threadIdx.x;
    float lg = -1e30f;
    if (tid < 60) {
        int rec = v*60 + tid;
        int sg = tid / 15, pp = tid % 15;
        int f = v*64 + sg*16 + pp;
        const float* av = g_avg + rec*512;
        const float* w  = lw + c*6784 + 6272;
        float dot = 0.f;
        #pragma unroll 4
        for (int k = 0; k < 512; k++) dot += av[k]*w[k];
        lg = 0.5f*(g_fdot[f*NCLS + c] + g_fdot[(f+1)*NCLS + c]) + dot + lb[c];
    }
    for (int off = 16; off; off >>= 1)
        lg = fmaxf(lg, __shfl_xor_sync(0xffffffffu, lg, off));
    __shared__ float red[2];
    if ((tid & 31) == 0) red[tid >> 5] = lg;
    __syncthreads();
    if (tid == 0) {
        float m = fmaxf(red[0], red[1]);
        out[v*NCLS + c] = 1.f / (1.f + expf(-m));
    }
}

// ================= launch =================
extern "C" void kernel_launch(void* const* d_in, const int* in_sizes, int n_in,
                              void* d_out, int out_size)
{
    const float* img  = (const float*)d_in[0];
    const int*   txt  = (const int*)d_in[1];
    const int*   lens = (const int*)d_in[2];
    const float* emb  = (const float*)d_in[7];
    const float* Wih0 = (const float*)d_in[8];
    const float* Whh0 = (const float*)d_in[9];
    const float* bih0 = (const float*)d_in[10];
    const float* bhh0 = (const float*)d_in[11];
    const float* Wih1 = (const float*)d_in[12];
    const float* Whh1 = (const float*)d_in[13];
    const float* bih1 = (const float*)d_in[14];
    const float* bhh1 = (const float*)d_in[15];
    const float* cw   = (const float*)d_in[16];
    const float* cb   = (const float*)d_in[17];
    const float* lw   = (const float*)d_in[18];
    const float* lb   = (const float*)d_in[19];
    float* out = (float*)d_out;

    static cudaStream_t s1 = nullptr;
    static cudaEvent_t evF = nullptr, evJ = nullptr;
    if (s1 == nullptr) {
        cudaStreamCreateWithFlags(&s1, cudaStreamNonBlocking);
        cudaEventCreateWithFlags(&evF, cudaEventDisableTiming);
        cudaEventCreateWithFlags(&evJ, cudaEventDisableTiming);
        cudaFuncSetAttribute(conv_mma_kernel,
                             cudaFuncAttributeMaxDynamicSharedMemorySize, CONV_SMEM);
    }

    pad_wih_kernel<<<2048, 128>>>(Wih0);                          // my #1
    embed_kernel<<<7680, 128>>>(txt, emb);                        // my #2
    gemm_kernel<<<dim3(60,8,2), 256>>>(0, (const float*)nullptr, bih0, bhh0); // my #3

    cudaEventRecord(evF, 0);
    cudaStreamWaitEvent(s1, evF, 0);
    conv_mma_kernel<<<dim3(14,64,8), 224, CONV_SMEM, s1>>>(img, cw); // my #4 <- profiled
    fdot_kernel<<<256, 256, 0, s1>>>(cb, lw);                     // my #5 (s1)

    zero_sync_kernel<<<1, 32>>>();
    lstm_seq<<<dim3(15,4,2), 256>>>(0, Whh0, lens);
    gemm_kernel<<<dim3(60,8,2), 256>>>(1, Wih1, bih1, bhh1);
    zero_sync_kernel<<<1, 32>>>();
    lstm_seq<<<dim3(15,4,2), 256>>>(1, Whh1, lens);
    avg_kernel<<<240, 512>>>(lens);

    cudaEventRecord(evJ, s1);
    cudaStreamWaitEvent(0, evJ, 0);
    final_kernel<<<80, 64>>>(lw, lb, out);
}

// round 15
// speedup vs baseline: 1.4124x; 1.3258x over previous
#include <cuda_runtime.h>
#include <math.h>

// ---------------- problem constants ----------------
#define NVID  4
#define FPV   64
#define TOTF  256
#define NRECS 240
#define TTXT  32
#define EPAD  304
#define HIDN  256
#define NCLS  20
#define OCC   32
#define MROWS 7680

typedef unsigned long long u64;

__device__ __forceinline__ u64 pk2(float lo, float hi) {
    u64 r; asm("mov.b64 %0, {%1, %2};" : "=l"(r) : "f"(lo), "f"(hi)); return r;
}
__device__ __forceinline__ void fma2(u64& d, u64 a, u64 b) {
    asm("fma.rn.f32x2 %0, %1, %2, %0;" : "+l"(d) : "l"(a), "l"(b));
}
__device__ __forceinline__ float2 upk2(u64 v) {
    float2 f; asm("mov.b64 {%0, %1}, %2;" : "=f"(f.x), "=f"(f.y) : "l"(v)); return f;
}

// ---------------- device-global scratch ----------------
__device__ float g_part[NVID*OCC*FPV*196];
__device__ float g_fdot[TOTF*NCLS];
__device__ float g_x0[MROWS*EPAD];
__device__ float g_wpad[2*1024*EPAD];
__device__ float g_pre[2*MROWS*1024];
__device__ float g_out0[MROWS*512];
__device__ float g_out1[MROWS*512];
__device__ float g_h[2][2][NRECS*HIDN];
__device__ float g_avg[NRECS*512];
__device__ unsigned g_sync[2][15];

// ================= Conv3D + HW max-pool via tf32 mma.sync, 2 d/CTA ==========
// grid (14 ph, 32 dpair, v*2+half), 448 threads = 14 warps (7 per depth).
// Slabs: parity-rotated double buffer, depth dd -> buffer dd&1.
// W: [(kd*7+kh)*4+p][k8][40] tf32, shared by both depth groups.
#define SB_WORDS (21*4*128)          // 10752 per slab
#define W_WORDS (21*4*8*40)          // 26880
#define CONV_SMEM ((2*SB_WORDS + W_WORDS)*4)   // 193536 B

__device__ __forceinline__ void conv_fill_slab(
    float* S, int dd, const float* __restrict__ img,
    int v, int ph, int half, int tid)
{
    for (int i = tid; i < 21*4*118; i += 448) {
        int w = i % 118; int rr = i / 118;
        int ci = rr & 3; int hp = rr >> 2;
        float val = 0.f;
        if (ci < 3 && (unsigned)dd < 64u) {
            int h_in = 16*ph - 3 + hp;
            int w_in = 112*half - 3 + w;
            if ((unsigned)h_in < 224u && (unsigned)w_in < 224u)
                val = img[(((v*64 + dd)*3 + ci)*224 + h_in)*224 + w_in];
        }
        unsigned uv; asm("cvt.rna.tf32.f32 %0, %1;" : "=r"(uv) : "f"(val));
        S[(hp*4 + ci)*128 + (w ^ (ci << 3))] = __uint_as_float(uv);
    }
}

__global__ __launch_bounds__(448,1) void conv_mma_kernel(
    const float* __restrict__ img, const float* __restrict__ cw)
{
    extern __shared__ float sh[];
    float* SBUF[2] = { sh, sh + SB_WORDS };
    float* W = sh + 2*SB_WORDS;
    const int ph = blockIdx.x;
    const int d0 = blockIdx.y * 2;
    const int v  = blockIdx.z >> 1, half = blockIdx.z & 1;
    const int tid = threadIdx.x;
    const int lane = tid & 31, wp = tid >> 5;
    const int g = wp / 7, wpc = wp % 7;
    const int wm = lane >> 2, qi = lane & 3;

    // ---- weight fill (tf32 bits) ----
    for (int i = tid; i < 21*4*8*32; i += 448) {
        int oc = i & 31; int rr = i >> 5;
        int k = rr & 7;  rr >>= 3;
        int p = rr & 3;  int kdkh = rr >> 2;
        int kw = 2*p + (k >> 2), ci = k & 3;
        float val = 0.f;
        if (kw < 7 && ci < 3) {
            int kd = kdkh / 7, kh = kdkh % 7;
            val = cw[(((oc*3 + ci)*3 + kd)*7 + kh)*7 + kw];
        }
        unsigned uv; asm("cvt.rna.tf32.f32 %0, %1;" : "=r"(uv) : "f"(val));
        W[(kdkh*4 + p)*8*40 + k*40 + oc] = __uint_as_float(uv);
    }
    conv_fill_slab(SBUF[(d0-1) & 1], d0-1, img, v, ph, half, tid);
    conv_fill_slab(SBUF[d0 & 1],     d0,   img, v, ph, half, tid);
    __syncthreads();

    float c[4][4][4];
    #pragma unroll
    for (int mt = 0; mt < 4; mt++)
        #pragma unroll
        for (int nt = 0; nt < 4; nt++)
            #pragma unroll
            for (int r = 0; r < 4; r++) c[mt][nt][r] = 0.f;

    const int wbase = 2*(wpc*8 + wm);
    const int sw = qi << 3;

    for (int kd = 0; kd < 3; kd++) {
        if (kd) {
            __syncthreads();
            conv_fill_slab(SBUF[(d0 + kd) & 1], d0 + kd, img, v, ph, half, tid);
            __syncthreads();
        }
        const float* S = SBUF[(d0 + g + kd - 1) & 1];

        for (int kh = 0; kh < 7; kh++) {
            unsigned b[4][4][2];
            const float* Wb = W + (kd*7 + kh)*4*8*40;
            #pragma unroll
            for (int p = 0; p < 4; p++)
                #pragma unroll
                for (int nt = 0; nt < 4; nt++) {
                    b[p][nt][0] = __float_as_uint(Wb[(p*8 + qi)*40 + nt*8 + wm]);
                    b[p][nt][1] = __float_as_uint(Wb[(p*8 + qi + 4)*40 + nt*8 + wm]);
                }
            #pragma unroll
            for (int mt = 0; mt < 4; mt++) {
                const float* A0 = S + ((4*mt + kh)*4 + qi)*128;
                const float* A1 = A0 + 2*4*128;
                float2 p0[4], p1[4];
                #pragma unroll
                for (int j = 0; j < 4; j++) {
                    p0[j] = *(const float2*)&A0[(wbase + 2*j) ^ sw];
                    p1[j] = *(const float2*)&A1[(wbase + 2*j) ^ sw];
                }
                #pragma unroll
                for (int p = 0; p < 4; p++) {
                    unsigned ra0 = __float_as_uint(p0[p].x);
                    unsigned ra2 = __float_as_uint(p0[p].y);
                    unsigned ra1 = __float_as_uint(p1[p].x);
                    unsigned ra3 = __float_as_uint(p1[p].y);
                    #pragma unroll
                    for (int nt = 0; nt < 4; nt++)
                        asm volatile(
                          "mma.sync.aligned.m16n8k8.row.col.f32.tf32.tf32.f32 "
                          "{%0,%1,%2,%3},{%4,%5,%6,%7},{%8,%9},{%0,%1,%2,%3};"
                          : "+f"(c[mt][nt][0]), "+f"(c[mt][nt][1]),
                            "+f"(c[mt][nt][2]), "+f"(c[mt][nt][3])
                          : "r"(ra0), "r"(ra1), "r"(ra2), "r"(ra3),
                            "r"(b[p][nt][0]), "r"(b[p][nt][1]));
                }
            }
        }
    }

    // ---- HW max-pool epilogue ----
    const int d  = d0 + g;
    const int pw = half*7 + wpc;
    #pragma unroll
    for (int nt = 0; nt < 4; nt++) {
        float m0 = -1e30f, m1 = -1e30f;
        #pragma unroll
        for (int mt = 0; mt < 4; mt++) {
            m0 = fmaxf(m0, fmaxf(c[mt][nt][0], c[mt][nt][2]));
            m1 = fmaxf(m1, fmaxf(c[mt][nt][1], c[mt][nt][3]));
        }
        #pragma unroll
        for (int off = 16; off >= 4; off >>= 1) {
            m0 = fmaxf(m0, __shfl_xor_sync(0xffffffffu, m0, off));
            m1 = fmaxf(m1, __shfl_xor_sync(0xffffffffu, m1, off));
        }
        if (wm == 0) {
            int oc = nt*8 + qi*2;
            int base = ((v*OCC + oc)*FPV + d)*196 + ph*14 + pw;
            g_part[base] = m0;
            g_part[base + FPV*196] = m1;
        }
    }
}

// ================= D-pool + (pooled features) . lin_w -> g_fdot =================
__global__ void fdot_kernel(const float* __restrict__ cb, const float* __restrict__ lw)
{
    const int f = blockIdx.x;
    const int v = f >> 6, d = f & 63;
    const int tid = threadIdx.x;
    float acc[NCLS];
    #pragma unroll
    for (int c = 0; c < NCLS; c++) acc[c] = 0.f;

    for (int k = tid; k < 6272; k += 256) {
        int oc = k / 196; int rem2 = k % 196;
        const float* base = g_part + (v*OCC + oc)*FPV*196 + rem2;
        float val = base[d*196];
        if (d > 0)  val = fmaxf(val, base[(d-1)*196]);
        if (d < 63) val = fmaxf(val, base[(d+1)*196]);
        val += cb[oc];
        #pragma unroll
        for (int c = 0; c < NCLS; c++) acc[c] = fmaf(val, lw[c*6784 + k], acc[c]);
    }
    #pragma unroll
    for (int c = 0; c < NCLS; c++)
        for (int off = 16; off; off >>= 1)
            acc[c] += __shfl_xor_sync(0xffffffffu, acc[c], off);

    __shared__ float red[8][NCLS];
    const int wid = tid >> 5, lane = tid & 31;
    if (lane == 0)
        #pragma unroll
        for (int c = 0; c < NCLS; c++) red[wid][c] = acc[c];
    __syncthreads();
    if (tid < NCLS) {
        float s = 0.f;
        #pragma unroll
        for (int w = 0; w < 8; w++) s += red[w][tid];
        g_fdot[f*NCLS + tid] = s;
    }
}

// ================= fused embed + Wih pad =================
__global__ void prep_kernel(const int* __restrict__ txt, const float* __restrict__ emb,
                            const float* __restrict__ Wih0)
{
    const int bx = blockIdx.x;
    if (bx < MROWS) {
        const int tok = txt[bx];
        const float* e = emb + (long long)tok * 300;
        for (int k = threadIdx.x; k < EPAD; k += 128)
            g_x0[bx*EPAD + k] = (k < 300) ? e[k] : 0.f;
    } else {
        const int row = bx - MROWS;
        const float* src = Wih0 + row * 300;
        for (int k = threadIdx.x; k < EPAD; k += 128)
            g_wpad[row*EPAD + k] = (k < 300) ? src[k] : 0.f;
    }
}

// ================= SGEMM: pre = X @ Wih^T + bih + bhh =================
__global__ __launch_bounds__(256,2) void gemm_kernel(
    int layer, const float* __restrict__ Bext,
    const float* __restrict__ bih, const float* __restrict__ bhh)
{
    const int K = layer ? 512 : EPAD;
    const float* A = layer ? g_out0 : g_x0;
    const float* B = (layer ? Bext : (const float*)g_wpad) + blockIdx.z * 1024 * K;
    float* C = g_pre + blockIdx.z * (MROWS * 1024);
    const int m0 = blockIdx.x * 128, n0 = blockIdx.y * 128;

    __shared__ float As[8*132];
    __shared__ float Bs[8*132];
    const int tid = threadIdx.x;
    const int lr = tid >> 1;
    const int lk = (tid & 1) * 4;
    const int ty = tid >> 4, tx = tid & 15;
    const float* Arow = A + (m0 + lr)*K + lk;
    const float* Brow = B + (n0 + lr)*K + lk;

    u64 accp[8][4];
    #pragma unroll
    for (int i = 0; i < 8; i++)
        #pragma unroll
        for (int p = 0; p < 4; p++) accp[i][p] = 0ull;

    for (int k0 = 0; k0 < K; k0 += 8) {
        float4 va = *(const float4*)(Arow + k0);
        float4 vb = *(const float4*)(Brow + k0);
        __syncthreads();
        As[(lk+0)*132 + lr] = va.x; As[(lk+1)*132 + lr] = va.y;
        As[(lk+2)*132 + lr] = va.z; As[(lk+3)*132 + lr] = va.w;
        Bs[(lk+0)*132 + lr] = vb.x; Bs[(lk+1)*132 + lr] = vb.y;
        Bs[(lk+2)*132 + lr] = vb.z; Bs[(lk+3)*132 + lr] = vb.w;
        __syncthreads();
        #pragma unroll
        for (int kk = 0; kk < 8; kk++) {
            float a[8];
            float4 t0 = *(const float4*)&As[kk*132 + ty*8];
            float4 t1 = *(const float4*)&As[kk*132 + ty*8 + 4];
            float4 t2 = *(const float4*)&Bs[kk*132 + tx*8];
            float4 t3 = *(const float4*)&Bs[kk*132 + tx*8 + 4];
            a[0]=t0.x;a[1]=t0.y;a[2]=t0.z;a[3]=t0.w;a[4]=t1.x;a[5]=t1.y;a[6]=t1.z;a[7]=t1.w;
            u64 bp[4];
            bp[0] = pk2(t2.x, t2.y); bp[1] = pk2(t2.z, t2.w);
            bp[2] = pk2(t3.x, t3.y); bp[3] = pk2(t3.z, t3.w);
            #pragma unroll
            for (int i = 0; i < 8; i++) {
                u64 a2 = pk2(a[i], a[i]);
                #pragma unroll
                for (int p = 0; p < 4; p++) fma2(accp[i][p], a2, bp[p]);
            }
        }
    }
    float bb[8];
    #pragma unroll
    for (int j = 0; j < 8; j++) {
        int n = n0 + tx*8 + j;
        bb[j] = bih[blockIdx.z*1024 + n] + bhh[blockIdx.z*1024 + n];
    }
    #pragma unroll
    for (int i = 0; i < 8; i++) {
        float* crow = C + (m0 + ty*8 + i)*1024 + n0 + tx*8;
        #pragma unroll
        for (int p = 0; p < 4; p++) {
            float2 f = upk2(accp[i][p]);
            crow[2*p]   = f.x + bb[2*p];
            crow[2*p+1] = f.y + bb[2*p+1];
        }
    }
}

// ================= LSTM: persistent 32-step kernel =================
__global__ void zero_sync_kernel()
{
    int i = threadIdx.x;
    if (i < 30) ((unsigned*)g_sync)[i] = 0u;
}

__global__ __launch_bounds__(256,1) void lstm_seq(
    int layer, int cbase, const float* __restrict__ Whh, const int* __restrict__ lens)
{
    const int r0  = blockIdx.x * 16;
    const int j0  = blockIdx.y * 64;
    const int dir = blockIdx.z;
    const float* pre = g_pre + dir * (MROWS * 1024);
    float* outb = layer ? g_out1 : g_out0;

    __shared__ float hs2[256][18];
    __shared__ float zs[4][64][17];
    __shared__ float cs[16][64];
    const int tid = threadIdx.x;
    const int jl = tid & 63, gt = tid >> 6;
    const int gidx = gt*256 + j0 + jl;
    const float* wrow = Whh + dir*1024*256 + gidx*256;
    unsigned* ctr = &g_sync[dir][blockIdx.x];

    for (int i = tid; i < 4096; i += 256) hs2[i & 255][i >> 8] = 0.f;
    for (int i = tid; i < 1024; i += 256) cs[i >> 6][i & 63] = 0.f;
    __syncthreads();

    for (int s = 0; s < 32; s++) {
        const int t = dir ? (31 - s) : s;

        u64 accp[8];
        #pragma unroll
        for (int q = 0; q < 8; q++)
            accp[q] = pk2(pre[((r0 + 2*q)*32 + t)*1024 + gidx],
                          pre[((r0 + 2*q + 1)*32 + t)*1024 + gidx]);

        #pragma unroll 2
        for (int k0 = 0; k0 < 256; k0 += 4) {
            float4 w = *(const float4*)(wrow + k0);
            float wk[4] = {w.x, w.y, w.z, w.w};
            #pragma unroll
            for (int kk = 0; kk < 4; kk++) {
                u64 w2 = pk2(wk[kk], wk[kk]);
                const u64* hrow = (const u64*)&hs2[k0 + kk][0];
                #pragma unroll
                for (int q = 0; q < 8; q++) fma2(accp[q], w2, hrow[q]);
            }
        }
        #pragma unroll
        for (int q = 0; q < 8; q++) {
            float2 f = upk2(accp[q]);
            zs[gt][jl][2*q]   = f.x;
            zs[gt][jl][2*q+1] = f.y;
        }
        __syncthreads();

        float* hn = g_h[(s + 1) & 1][dir];
        #pragma unroll
        for (int q = 0; q < 4; q++) {
            int cell = tid + 256*q;
            int jl2 = cell & 63, rr = cell >> 6;
            int row = r0 + rr, j = j0 + jl2;
            float zi = zs[0][jl2][rr], zf = zs[1][jl2][rr];
            float zg = zs[2][jl2][rr], zo = zs[3][jl2][rr];
            float c_old = cs[rr][jl2];
            float h_old = hs2[j][rr];
            bool m = t < lens[row];
            float si = 1.f / (1.f + expf(-zi));
            float sf = 1.f / (1.f + expf(-zf));
            float so = 1.f / (1.f + expf(-zo));
            float cn = sf*c_old + si*tanhf(zg);
            float hv = so*tanhf(cn);
            cs[rr][jl2] = m ? cn : c_old;
            hn[row*256 + j] = m ? hv : h_old;
            outb[(row*32 + t)*512 + dir*256 + j] = m ? hv : 0.f;
        }

        if (s < 31) {
            __syncthreads();            // all threads' hn stores issued (CTA-scope order)
            if (tid == 0) {
                // release-add then acquire-poll (grid.sync pattern; no full MEMBAR)
                asm volatile("red.release.gpu.global.add.u32 [%0], 1;"
                             :: "l"(ctr) : "memory");
                unsigned target = (unsigned)(cbase + 4*(s + 1));
                unsigned cur;
                do {
                    asm volatile("ld.acquire.gpu.global.u32 %0, [%1];"
                                 : "=r"(cur) : "l"(ctr));
                } while (cur < target);
            }
            __syncthreads();
            const float* hp = g_h[(s + 1) & 1][dir];
            for (int i = tid; i < 4096; i += 256) {
                int r = i >> 8, k = i & 255;
                hs2[k][r] = __ldcg(&hp[(r0 + r)*256 + k]);
            }
            __syncthreads();
        }
    }
}

// ================= masked mean over time =================
__global__ void avg_kernel(const int* __restrict__ lens)
{
    const int row = blockIdx.x;
    const int k = threadIdx.x;
    float s = 0.f;
    for (int t = 0; t < 32; t++) s += g_out1[(row*32 + t)*512 + k];
    g_avg[row*512 + k] = s / (float)lens[row];
}

// ================= logits + per-video max + sigmoid =================
__global__ void final_kernel(const float* __restrict__ lw, const float* __restrict__ lb,
                             float* __restrict__ out)
{
    const int v = blockIdx.x / NCLS, c = blockIdx.x % NCLS;
    const int tid = threadIdx.x;
    float lg = -1e30f;
    if (tid < 60) {
        int rec = v*60 + tid;
        int sg = tid / 15, pp = tid % 15;
        int f = v*64 + sg*16 + pp;
        const float* av = g_avg + rec*512;
        const float* w  = lw + c*6784 + 6272;
        float dot = 0.f;
        #pragma unroll 4
        for (int k = 0; k < 512; k++) dot += av[k]*w[k];
        lg = 0.5f*(g_fdot[f*NCLS + c] + g_fdot[(f+1)*NCLS + c]) + dot + lb[c];
    }
    for (int off = 16; off; off >>= 1)
        lg = fmaxf(lg, __shfl_xor_sync(0xffffffffu, lg, off));
    __shared__ float red[2];
    if ((tid & 31) == 0) red[tid >> 5] = lg;
    __syncthreads();
    if (tid == 0) {
        float m = fmaxf(red[0], red[1]);
        out[v*NCLS + c] = 1.f / (1.f + expf(-m));
    }
}

// ================= launch =================
// ncu profiles overall #6 = my #4 = lstm_seq (layer 0).
extern "C" void kernel_launch(void* const* d_in, const int* in_sizes, int n_in,
                              void* d_out, int out_size)
{
    const float* img  = (const float*)d_in[0];
    const int*   txt  = (const int*)d_in[1];
    const int*   lens = (const int*)d_in[2];
    const float* emb  = (const float*)d_in[7];
    const float* Wih0 = (const float*)d_in[8];
    const float* Whh0 = (const float*)d_in[9];
    const float* bih0 = (const float*)d_in[10];
    const float* bhh0 = (const float*)d_in[11];
    const float* Wih1 = (const float*)d_in[12];
    const float* Whh1 = (const float*)d_in[13];
    const float* bih1 = (const float*)d_in[14];
    const float* bhh1 = (const float*)d_in[15];
    const float* cw   = (const float*)d_in[16];
    const float* cb   = (const float*)d_in[17];
    const float* lw   = (const float*)d_in[18];
    const float* lb   = (const float*)d_in[19];
    float* out = (float*)d_out;

    static cudaStream_t s1 = nullptr;
    static cudaEvent_t evF = nullptr, evJ = nullptr;
    if (s1 == nullptr) {
        cudaStreamCreateWithFlags(&s1, cudaStreamNonBlocking);
        cudaEventCreateWithFlags(&evF, cudaEventDisableTiming);
        cudaEventCreateWithFlags(&evJ, cudaEventDisableTiming);
        cudaFuncSetAttribute(conv_mma_kernel,
                             cudaFuncAttributeMaxDynamicSharedMemorySize, CONV_SMEM);
    }

    cudaEventRecord(evF, 0);
    cudaStreamWaitEvent(s1, evF, 0);

    prep_kernel<<<MROWS + 2048, 128>>>(txt, emb, Wih0);                 // my #1
    gemm_kernel<<<dim3(60,8,2), 256>>>(0, (const float*)nullptr, bih0, bhh0); // my #2
    zero_sync_kernel<<<1, 32>>>();                                      // my #3
    lstm_seq<<<dim3(15,4,2), 256>>>(0, 0, Whh0, lens);                  // my #4 <- profiled

    conv_mma_kernel<<<dim3(14,32,8), 448, CONV_SMEM, s1>>>(img, cw);    // my #5 (s1)
    fdot_kernel<<<256, 256, 0, s1>>>(cb, lw);                           // my #6 (s1)

    gemm_kernel<<<dim3(60,8,2), 256>>>(1, Wih1, bih1, bhh1);
    lstm_seq<<<dim3(15,4,2), 256>>>(1, 124, Whh1, lens);
    avg_kernel<<<240, 512>>>(lens);

    cudaEventRecord(evJ, s1);
    cudaStreamWaitEvent(0, evJ, 0);
    final_kernel<<<80, 64>>>(lw, lb, out);
}